// round 1
// baseline (speedup 1.0000x reference)
#include <cuda_runtime.h>

// Problem constants (fixed by setup_inputs: P=64, K=8, C=512, N=3*P*K=1536)
#define NROWS 1536
#define CDIM  512
#define MCL   192      // 3*P hard-cluster centers
#define GK    8        // instances per cluster
#define MARGIN_KL 6.0f
#define MID_N 1024     // NROWS//3*2
#define MID_M 128      // MCL//3*2
#define NBLK3 96       // kernel3 grid size (48 x 2)

// Scratch (static device allocations; no cudaMalloc allowed)
__device__ float g_xs[NROWS * CDIM];     // softmax(x)
__device__ float g_rowc[NROWS];          // ent_x[i] + lse[i]
__device__ float g_hcT[CDIM * MCL];      // hcen^T  (k-major)
__device__ float g_lhT[CDIM * MCL];      // logh^T  (k-major)
__device__ float g_enth[MCL];            // sum hcen*logh per cluster
__device__ float g_part[NBLK3 * 4];      // per-block partial {psum, nsum, pcnt, ncnt}

// ---------------------------------------------------------------------------
// Kernel 1: per-row softmax stats. 1536 blocks x 128 threads, 1 float4/thread.
// Computes xs, and rowc = ent_x + lse  (ent_x = sum xs*(x-lse)).
// ---------------------------------------------------------------------------
__global__ void __launch_bounds__(128) k_softmax(const float* __restrict__ x) {
    __shared__ float smax[4], ssum[4], sent[4];
    const int row = blockIdx.x;
    const int t = threadIdx.x;
    const int w = t >> 5, lane = t & 31;

    float4 v = reinterpret_cast<const float4*>(x + row * CDIM)[t];

    // max
    float mx = fmaxf(fmaxf(v.x, v.y), fmaxf(v.z, v.w));
    #pragma unroll
    for (int o = 16; o; o >>= 1) mx = fmaxf(mx, __shfl_xor_sync(0xffffffffu, mx, o));
    if (lane == 0) smax[w] = mx;
    __syncthreads();
    mx = fmaxf(fmaxf(smax[0], smax[1]), fmaxf(smax[2], smax[3]));

    // sum exp
    float e0 = __expf(v.x - mx), e1 = __expf(v.y - mx);
    float e2 = __expf(v.z - mx), e3 = __expf(v.w - mx);
    float s = (e0 + e1) + (e2 + e3);
    #pragma unroll
    for (int o = 16; o; o >>= 1) s += __shfl_xor_sync(0xffffffffu, s, o);
    if (lane == 0) ssum[w] = s;
    __syncthreads();
    float S = (ssum[0] + ssum[1]) + (ssum[2] + ssum[3]);

    float lse = mx + __logf(S);
    float inv = 1.0f / S;
    float4 p = make_float4(e0 * inv, e1 * inv, e2 * inv, e3 * inv);
    reinterpret_cast<float4*>(g_xs + row * CDIM)[t] = p;

    // ent_x partial = sum xs * (x - lse)
    float ent = p.x * (v.x - lse) + p.y * (v.y - lse)
              + p.z * (v.z - lse) + p.w * (v.w - lse);
    #pragma unroll
    for (int o = 16; o; o >>= 1) ent += __shfl_xor_sync(0xffffffffu, ent, o);
    if (lane == 0) sent[w] = ent;
    __syncthreads();
    if (t == 0) {
        float e = (sent[0] + sent[1]) + (sent[2] + sent[3]);
        g_rowc[row] = e + lse;
    }
}

// ---------------------------------------------------------------------------
// Kernel 2: hard-cluster centers. 192 blocks x 128 threads (1 float4/thread).
// hcen = mean of 8 xs rows; stores hcen^T and logh^T k-major; ent_h reduce.
// ---------------------------------------------------------------------------
__global__ void __launch_bounds__(128) k_hcen() {
    __shared__ float sred[4];
    const int j = blockIdx.x;
    const int t = threadIdx.x;
    const int w = t >> 5, lane = t & 31;

    const float4* base = reinterpret_cast<const float4*>(g_xs + (size_t)j * GK * CDIM);
    float4 s = make_float4(0.f, 0.f, 0.f, 0.f);
    #pragma unroll
    for (int r = 0; r < GK; r++) {
        float4 v = base[r * (CDIM / 4) + t];
        s.x += v.x; s.y += v.y; s.z += v.z; s.w += v.w;
    }
    const float invg = 1.0f / (float)GK;
    s.x *= invg; s.y *= invg; s.z *= invg; s.w *= invg;

    float4 l;
    l.x = __logf(fmaxf(s.x, 1e-9f));
    l.y = __logf(fmaxf(s.y, 1e-9f));
    l.z = __logf(fmaxf(s.z, 1e-9f));
    l.w = __logf(fmaxf(s.w, 1e-9f));

    const int k0 = 4 * t;
    g_hcT[(k0 + 0) * MCL + j] = s.x;
    g_hcT[(k0 + 1) * MCL + j] = s.y;
    g_hcT[(k0 + 2) * MCL + j] = s.z;
    g_hcT[(k0 + 3) * MCL + j] = s.w;
    g_lhT[(k0 + 0) * MCL + j] = l.x;
    g_lhT[(k0 + 1) * MCL + j] = l.y;
    g_lhT[(k0 + 2) * MCL + j] = l.z;
    g_lhT[(k0 + 3) * MCL + j] = l.w;

    float ent = s.x * l.x + s.y * l.y + s.z * l.z + s.w * l.w;
    #pragma unroll
    for (int o = 16; o; o >>= 1) ent += __shfl_xor_sync(0xffffffffu, ent, o);
    if (lane == 0) sred[w] = ent;
    __syncthreads();
    if (t == 0) g_enth[j] = (sred[0] + sred[1]) + (sred[2] + sred[3]);
}

// ---------------------------------------------------------------------------
// Kernel 3: fused dual-GEMM + loss epilogue.
// dist[i,j] = rowc[i] + enth[j] - x_i.hcen_j - xs_i.logh_j
// Block tile 32 rows x 96 cols, K-chunk 32, thread tile 4x6, 128 threads.
// Grid (48, 2) = 96 blocks. Loss contributions reduced per block (deterministic).
// ---------------------------------------------------------------------------
__global__ void __launch_bounds__(128) k_dist(const float* __restrict__ x,
                                              const long long* __restrict__ pids) {
    __shared__ float sax[32][33];    // [row][kk]  x tile
    __shared__ float sas[32][33];    // [row][kk]  xs tile
    __shared__ float sbh[32][104];   // [kk][j]    hcen tile
    __shared__ float sbl[32][104];   // [kk][j]    logh tile

    const int bi = blockIdx.x;       // 0..47 (row tile)
    const int bj = blockIdx.y;       // 0..1  (col tile of 96)
    const int t = threadIdx.x;
    const int ti = t & 7;            // row group: rows ti*4..ti*4+3
    const int tj = t >> 3;           // col group: cols tj*6..tj*6+5

    float acc[4][6];
    #pragma unroll
    for (int r = 0; r < 4; r++)
        #pragma unroll
        for (int c = 0; c < 6; c++) acc[r][c] = 0.f;

    const int arow = t >> 2;         // 0..31
    const int acol = (t & 3) * 4;    // 0,4,8,12

    for (int k0 = 0; k0 < CDIM; k0 += 32) {
        // load A tiles (x, xs): 32 rows x 32 k, 2 float4 per thread per array
        #pragma unroll
        for (int h = 0; h < 2; h++) {
            const int kk = acol + 16 * h;
            const int gidx = (bi * 32 + arow) * CDIM + k0 + kk;
            float4 xv = *reinterpret_cast<const float4*>(x + gidx);
            sax[arow][kk + 0] = xv.x; sax[arow][kk + 1] = xv.y;
            sax[arow][kk + 2] = xv.z; sax[arow][kk + 3] = xv.w;
            float4 sv = *reinterpret_cast<const float4*>(g_xs + gidx);
            sas[arow][kk + 0] = sv.x; sas[arow][kk + 1] = sv.y;
            sas[arow][kk + 2] = sv.z; sas[arow][kk + 3] = sv.w;
        }
        // load B tiles (hcen^T, logh^T): 32 k x 96 j, coalesced, 6 float4/thread
        #pragma unroll
        for (int sblk = 0; sblk < 6; sblk++) {
            const int f = t + 128 * sblk;        // 0..767
            const int kk = f / 24;
            const int jf = (f % 24) * 4;
            const int gidx = (k0 + kk) * MCL + bj * 96 + jf;
            *reinterpret_cast<float4*>(&sbh[kk][jf]) =
                *reinterpret_cast<const float4*>(g_hcT + gidx);
            *reinterpret_cast<float4*>(&sbl[kk][jf]) =
                *reinterpret_cast<const float4*>(g_lhT + gidx);
        }
        __syncthreads();

        #pragma unroll 4
        for (int kk = 0; kk < 32; kk++) {
            float a0[4], a1[4], b0[6], b1[6];
            #pragma unroll
            for (int r = 0; r < 4; r++) {
                a0[r] = sax[ti * 4 + r][kk];
                a1[r] = sas[ti * 4 + r][kk];
            }
            #pragma unroll
            for (int c = 0; c < 6; c++) {
                b0[c] = sbh[kk][tj * 6 + c];
                b1[c] = sbl[kk][tj * 6 + c];
            }
            #pragma unroll
            for (int r = 0; r < 4; r++)
                #pragma unroll
                for (int c = 0; c < 6; c++) {
                    acc[r][c] += a0[r] * b0[c];
                    acc[r][c] += a1[r] * b1[c];
                }
        }
        __syncthreads();
    }

    // Epilogue: classify each dist, accumulate loss terms
    const int ibase = bi * 32 + ti * 4;
    const int jbase = bj * 96 + tj * 6;

    float rc[4]; long long pid[4];
    #pragma unroll
    for (int r = 0; r < 4; r++) {
        rc[r] = g_rowc[ibase + r];
        pid[r] = pids[ibase + r];
    }
    float eh[6]; long long ph[6];
    #pragma unroll
    for (int c = 0; c < 6; c++) {
        eh[c] = g_enth[jbase + c];
        ph[c] = pids[(long long)(jbase + c) * GK];   // pidhc[j]
    }

    float psum = 0.f, nsum = 0.f;
    int pcnt = 0, ncnt = 0;
    #pragma unroll
    for (int r = 0; r < 4; r++) {
        const bool itop = (ibase + r) < MID_N;
        #pragma unroll
        for (int c = 0; c < 6; c++) {
            const float dist = rc[r] + eh[c] - acc[r][c];
            const bool mask = (pid[r] == ph[c]);
            const bool region = itop != ((jbase + c) < MID_M);
            if (mask) {
                if (region) { psum += dist; pcnt++; }
            } else {
                nsum += fmaxf(MARGIN_KL - dist, 0.f);
                ncnt++;
            }
        }
    }

    // deterministic block reduction (warp shuffle, fixed order)
    #pragma unroll
    for (int o = 16; o; o >>= 1) {
        psum += __shfl_xor_sync(0xffffffffu, psum, o);
        nsum += __shfl_xor_sync(0xffffffffu, nsum, o);
        pcnt += __shfl_xor_sync(0xffffffffu, pcnt, o);
        ncnt += __shfl_xor_sync(0xffffffffu, ncnt, o);
    }
    __shared__ float rp[4], rn[4];
    __shared__ int cp[4], cn[4];
    const int w = t >> 5;
    if ((t & 31) == 0) { rp[w] = psum; rn[w] = nsum; cp[w] = pcnt; cn[w] = ncnt; }
    __syncthreads();
    if (t == 0) {
        const int blk = bi * 2 + bj;
        g_part[blk * 4 + 0] = (rp[0] + rp[1]) + (rp[2] + rp[3]);
        g_part[blk * 4 + 1] = (rn[0] + rn[1]) + (rn[2] + rn[3]);
        g_part[blk * 4 + 2] = (float)((cp[0] + cp[1]) + (cp[2] + cp[3]));
        g_part[blk * 4 + 3] = (float)((cn[0] + cn[1]) + (cn[2] + cn[3]));
    }
}

// ---------------------------------------------------------------------------
// Kernel 4: final deterministic reduction over 96 block partials -> scalar.
// ---------------------------------------------------------------------------
__global__ void k_final(float* __restrict__ out) {
    const int t = threadIdx.x;  // 32 threads
    float ps = 0.f, ns = 0.f, pc = 0.f, nc = 0.f;
    for (int b = t; b < NBLK3; b += 32) {
        ps += g_part[b * 4 + 0];
        ns += g_part[b * 4 + 1];
        pc += g_part[b * 4 + 2];
        nc += g_part[b * 4 + 3];
    }
    #pragma unroll
    for (int o = 16; o; o >>= 1) {
        ps += __shfl_xor_sync(0xffffffffu, ps, o);
        ns += __shfl_xor_sync(0xffffffffu, ns, o);
        pc += __shfl_xor_sync(0xffffffffu, pc, o);
        nc += __shfl_xor_sync(0xffffffffu, nc, o);
    }
    if (t == 0) {
        const float loss1 = ps / fmaxf(pc, 1.0f);
        const float loss2 = ns / fmaxf(nc, 1.0f);
        out[0] = loss1 + loss2;   // K1 = K2 = 1
    }
}

// ---------------------------------------------------------------------------
extern "C" void kernel_launch(void* const* d_in, const int* in_sizes, int n_in,
                              void* d_out, int out_size) {
    const float* x = (const float*)d_in[0];
    const long long* pids = (const long long*)d_in[1];
    (void)in_sizes; (void)n_in; (void)out_size;

    k_softmax<<<NROWS, 128>>>(x);
    k_hcen<<<MCL, 128>>>();
    dim3 g3(48, 2);
    k_dist<<<g3, 128>>>(x, pids);
    k_final<<<1, 32>>>((float*)d_out);
}

// round 2
// speedup vs baseline: 1.7585x; 1.7585x over previous
#include <cuda_runtime.h>

// Problem constants (fixed by setup_inputs: P=64, K=8, C=512, N=3*P*K=1536)
#define NROWS 1536
#define CDIM  512
#define MCL   192      // 3*P hard-cluster centers
#define GK    8        // instances per cluster
#define MARGIN_KL 6.0f
#define MID_N 1024     // NROWS//3*2
#define MID_M 128      // MCL//3*2
#define GBI   48       // dist grid x (row tiles of 32)
#define GBJ   3        // dist grid y (col tiles of 64)
#define NBLK  (GBI*GBJ)

// Static device scratch (no cudaMalloc allowed)
__device__ float g_xs[NROWS * CDIM];     // softmax(x)
__device__ float g_rowc[NROWS];          // ent_x[i] + lse[i]
__device__ float g_hcT[CDIM * MCL];      // hcen^T  (k-major: [k][j])
__device__ float g_lhT[CDIM * MCL];      // logh^T  (k-major: [k][j])
__device__ float g_enth[MCL];            // sum hcen*logh per cluster
__device__ float g_part[NBLK * 4];       // per-block partials {psum,nsum,pcnt,ncnt}
__device__ unsigned int g_ctr = 0;       // completion counter (reset by last block)

// ---------------- packed f32x2 helpers (Blackwell) ----------------
__device__ __forceinline__ unsigned long long pk2(float lo, float hi) {
    unsigned long long r;
    asm("mov.b64 %0, {%1, %2};" : "=l"(r) : "f"(lo), "f"(hi));
    return r;
}
__device__ __forceinline__ void fma2(unsigned long long& d,
                                     unsigned long long a, unsigned long long b) {
    asm("fma.rn.f32x2 %0, %1, %2, %0;" : "+l"(d) : "l"(a), "l"(b));
}
__device__ __forceinline__ void upk2(unsigned long long v, float& lo, float& hi) {
    asm("mov.b64 {%0, %1}, %2;" : "=f"(lo), "=f"(hi) : "l"(v));
}

// ---------------------------------------------------------------------------
// Kernel 1: fused softmax stats + hard-cluster centers.
// 192 blocks (one per cluster) x 256 threads (warp w handles row 8*j + w).
// Outputs: g_xs, g_rowc = ent_x + lse, g_hcT/g_lhT (k-major), g_enth.
// ---------------------------------------------------------------------------
__global__ void __launch_bounds__(256) k_stats(const float* __restrict__ x) {
    __shared__ float sxs[8][516];   // pad 516: 16B-aligned rows, conflict-free col reads
    __shared__ float sred[8];
    const int j = blockIdx.x;
    const int t = threadIdx.x;
    const int w = t >> 5, lane = t & 31;
    const int row = j * GK + w;

    const float4* xr = reinterpret_cast<const float4*>(x + (size_t)row * CDIM);
    float4 v[4];
    #pragma unroll
    for (int q = 0; q < 4; q++) v[q] = xr[lane + 32 * q];

    // row max
    float mx = -1e30f;
    #pragma unroll
    for (int q = 0; q < 4; q++)
        mx = fmaxf(mx, fmaxf(fmaxf(v[q].x, v[q].y), fmaxf(v[q].z, v[q].w)));
    #pragma unroll
    for (int o = 16; o; o >>= 1) mx = fmaxf(mx, __shfl_xor_sync(0xffffffffu, mx, o));

    // exp + sum (precise expf for accuracy margin)
    float4 e[4];
    float s = 0.f;
    #pragma unroll
    for (int q = 0; q < 4; q++) {
        e[q].x = expf(v[q].x - mx); e[q].y = expf(v[q].y - mx);
        e[q].z = expf(v[q].z - mx); e[q].w = expf(v[q].w - mx);
        s += (e[q].x + e[q].y) + (e[q].z + e[q].w);
    }
    #pragma unroll
    for (int o = 16; o; o >>= 1) s += __shfl_xor_sync(0xffffffffu, s, o);

    const float lse = mx + logf(s);
    const float inv = 1.0f / s;

    float4* gx = reinterpret_cast<float4*>(g_xs + (size_t)row * CDIM);
    float4* sx = reinterpret_cast<float4*>(&sxs[w][0]);
    float ent = 0.f;
    #pragma unroll
    for (int q = 0; q < 4; q++) {
        float4 p = make_float4(e[q].x * inv, e[q].y * inv, e[q].z * inv, e[q].w * inv);
        gx[lane + 32 * q] = p;
        sx[lane + 32 * q] = p;
        ent += p.x * (v[q].x - lse) + p.y * (v[q].y - lse)
             + p.z * (v[q].z - lse) + p.w * (v[q].w - lse);
    }
    #pragma unroll
    for (int o = 16; o; o >>= 1) ent += __shfl_xor_sync(0xffffffffu, ent, o);
    if (lane == 0) g_rowc[row] = ent + lse;

    __syncthreads();

    // centers: thread t handles columns t and t+256
    float entp = 0.f;
    #pragma unroll
    for (int h = 0; h < 2; h++) {
        const int c = t + 256 * h;
        float hc = 0.f;
        #pragma unroll
        for (int r = 0; r < GK; r++) hc += sxs[r][c];
        hc *= (1.0f / (float)GK);
        const float l = logf(fmaxf(hc, 1e-9f));
        g_hcT[c * MCL + j] = hc;
        g_lhT[c * MCL + j] = l;
        entp += hc * l;
    }
    #pragma unroll
    for (int o = 16; o; o >>= 1) entp += __shfl_xor_sync(0xffffffffu, entp, o);
    if (lane == 0) sred[w] = entp;
    __syncthreads();
    if (t == 0) {
        float eh = 0.f;
        #pragma unroll
        for (int r = 0; r < 8; r++) eh += sred[r];
        g_enth[j] = eh;
    }
}

// ---------------------------------------------------------------------------
// Kernel 2: fused dual-GEMM + loss epilogue + last-block final reduction.
// dist[i,j] = rowc[i] + enth[j] - x_i.hcen_j - xs_i.logh_j
// Block tile 32x64, thread tile 4x4, 128 threads, grid (48,3) = 144 blocks.
// Inner product uses packed fma.rn.f32x2 (2 FMA/instr).
// ---------------------------------------------------------------------------
__global__ void __launch_bounds__(128) k_dist(const float* __restrict__ x,
                                              const long long* __restrict__ pids,
                                              float* __restrict__ out) {
    __shared__ float sax[32][36];   // [kk][row]  x tile (k-major, pad 36 for v4 align)
    __shared__ float sas[32][36];   // [kk][row]  xs tile
    __shared__ float sbh[32][64];   // [kk][j]    hcen tile
    __shared__ float sbl[32][64];   // [kk][j]    logh tile

    const int bi = blockIdx.x;      // 0..47
    const int bj = blockIdx.y;      // 0..2
    const int t  = threadIdx.x;
    const int ti = t >> 4;          // 0..7  rows ti*4..+3
    const int tj = t & 15;          // 0..15 cols tj*4..+3

    // A loader mapping (32 rows x 32 kk, 2 float4 per array per thread)
    const int arow = t >> 2;        // 0..31
    const int acol = (t & 3) * 4;   // 0,4,8,12

    unsigned long long acc[4][2];
    #pragma unroll
    for (int r = 0; r < 4; r++) { acc[r][0] = 0ull; acc[r][1] = 0ull; }

    float4 ax0, ax1, as0, as1, bh[4], bl[4];

    // prefetch chunk 0
    {
        const size_t ga = (size_t)(bi * 32 + arow) * CDIM + acol;
        ax0 = *reinterpret_cast<const float4*>(x + ga);
        ax1 = *reinterpret_cast<const float4*>(x + ga + 16);
        as0 = *reinterpret_cast<const float4*>(g_xs + ga);
        as1 = *reinterpret_cast<const float4*>(g_xs + ga + 16);
        #pragma unroll
        for (int sb = 0; sb < 4; sb++) {
            const int idx = t + 128 * sb;
            const int kk = idx >> 4, jf = (idx & 15) * 4;
            const size_t gb = (size_t)kk * MCL + bj * 64 + jf;
            bh[sb] = *reinterpret_cast<const float4*>(g_hcT + gb);
            bl[sb] = *reinterpret_cast<const float4*>(g_lhT + gb);
        }
    }

    for (int ch = 0; ch < CDIM / 32; ch++) {
        // store staged tiles
        sax[acol + 0][arow] = ax0.x; sax[acol + 1][arow] = ax0.y;
        sax[acol + 2][arow] = ax0.z; sax[acol + 3][arow] = ax0.w;
        sax[acol + 16][arow] = ax1.x; sax[acol + 17][arow] = ax1.y;
        sax[acol + 18][arow] = ax1.z; sax[acol + 19][arow] = ax1.w;
        sas[acol + 0][arow] = as0.x; sas[acol + 1][arow] = as0.y;
        sas[acol + 2][arow] = as0.z; sas[acol + 3][arow] = as0.w;
        sas[acol + 16][arow] = as1.x; sas[acol + 17][arow] = as1.y;
        sas[acol + 18][arow] = as1.z; sas[acol + 19][arow] = as1.w;
        #pragma unroll
        for (int sb = 0; sb < 4; sb++) {
            const int idx = t + 128 * sb;
            const int kk = idx >> 4, jf = (idx & 15) * 4;
            *reinterpret_cast<float4*>(&sbh[kk][jf]) = bh[sb];
            *reinterpret_cast<float4*>(&sbl[kk][jf]) = bl[sb];
        }
        __syncthreads();

        // prefetch next chunk while computing
        if (ch < CDIM / 32 - 1) {
            const int k0 = (ch + 1) * 32;
            const size_t ga = (size_t)(bi * 32 + arow) * CDIM + k0 + acol;
            ax0 = *reinterpret_cast<const float4*>(x + ga);
            ax1 = *reinterpret_cast<const float4*>(x + ga + 16);
            as0 = *reinterpret_cast<const float4*>(g_xs + ga);
            as1 = *reinterpret_cast<const float4*>(g_xs + ga + 16);
            #pragma unroll
            for (int sb = 0; sb < 4; sb++) {
                const int idx = t + 128 * sb;
                const int kk = idx >> 4, jf = (idx & 15) * 4;
                const size_t gb = (size_t)(k0 + kk) * MCL + bj * 64 + jf;
                bh[sb] = *reinterpret_cast<const float4*>(g_hcT + gb);
                bl[sb] = *reinterpret_cast<const float4*>(g_lhT + gb);
            }
        }

        #pragma unroll 8
        for (int kk = 0; kk < 32; kk++) {
            const float4 avx = *reinterpret_cast<const float4*>(&sax[kk][ti * 4]);
            const float4 avs = *reinterpret_cast<const float4*>(&sas[kk][ti * 4]);
            const float4 bvh = *reinterpret_cast<const float4*>(&sbh[kk][tj * 4]);
            const float4 bvl = *reinterpret_cast<const float4*>(&sbl[kk][tj * 4]);
            const unsigned long long bh01 = pk2(bvh.x, bvh.y);
            const unsigned long long bh23 = pk2(bvh.z, bvh.w);
            const unsigned long long bl01 = pk2(bvl.x, bvl.y);
            const unsigned long long bl23 = pk2(bvl.z, bvl.w);
            const unsigned long long axd[4] = { pk2(avx.x, avx.x), pk2(avx.y, avx.y),
                                                pk2(avx.z, avx.z), pk2(avx.w, avx.w) };
            const unsigned long long asd[4] = { pk2(avs.x, avs.x), pk2(avs.y, avs.y),
                                                pk2(avs.z, avs.z), pk2(avs.w, avs.w) };
            #pragma unroll
            for (int r = 0; r < 4; r++) {
                fma2(acc[r][0], axd[r], bh01);
                fma2(acc[r][1], axd[r], bh23);
                fma2(acc[r][0], asd[r], bl01);
                fma2(acc[r][1], asd[r], bl23);
            }
        }
        __syncthreads();
    }

    // ---- epilogue: classify dist entries, accumulate loss terms ----
    const int ibase = bi * 32 + ti * 4;
    const int jbase = bj * 64 + tj * 4;

    float rc[4]; long long pid[4];
    #pragma unroll
    for (int r = 0; r < 4; r++) {
        rc[r] = g_rowc[ibase + r];
        pid[r] = pids[ibase + r];
    }
    float eh[4]; long long ph[4];
    #pragma unroll
    for (int c = 0; c < 4; c++) {
        eh[c] = g_enth[jbase + c];
        ph[c] = pids[(size_t)(jbase + c) * GK];   // pidhc[j]
    }

    float psum = 0.f, nsum = 0.f;
    int pcnt = 0, ncnt = 0;
    #pragma unroll
    for (int r = 0; r < 4; r++) {
        const bool itop = (ibase + r) < MID_N;
        float dv[4];
        upk2(acc[r][0], dv[0], dv[1]);
        upk2(acc[r][1], dv[2], dv[3]);
        #pragma unroll
        for (int c = 0; c < 4; c++) {
            const float dist = rc[r] + eh[c] - dv[c];
            const bool mask = (pid[r] == ph[c]);
            const bool region = itop != ((jbase + c) < MID_M);
            if (mask) {
                if (region) { psum += dist; pcnt++; }
            } else {
                nsum += fmaxf(MARGIN_KL - dist, 0.f);
                ncnt++;
            }
        }
    }

    // block reduction (deterministic fixed order)
    __shared__ float rp[4], rn[4];
    __shared__ int cp[4], cn[4];
    __shared__ bool slast;
    #pragma unroll
    for (int o = 16; o; o >>= 1) {
        psum += __shfl_xor_sync(0xffffffffu, psum, o);
        nsum += __shfl_xor_sync(0xffffffffu, nsum, o);
        pcnt += __shfl_xor_sync(0xffffffffu, pcnt, o);
        ncnt += __shfl_xor_sync(0xffffffffu, ncnt, o);
    }
    const int w = t >> 5;
    if ((t & 31) == 0) { rp[w] = psum; rn[w] = nsum; cp[w] = pcnt; cn[w] = ncnt; }
    __syncthreads();
    const int blk = bi * GBJ + bj;
    if (t == 0) {
        g_part[blk * 4 + 0] = (rp[0] + rp[1]) + (rp[2] + rp[3]);
        g_part[blk * 4 + 1] = (rn[0] + rn[1]) + (rn[2] + rn[3]);
        g_part[blk * 4 + 2] = (float)((cp[0] + cp[1]) + (cp[2] + cp[3]));
        g_part[blk * 4 + 3] = (float)((cn[0] + cn[1]) + (cn[2] + cn[3]));
        __threadfence();
        slast = (atomicAdd(&g_ctr, 1u) == NBLK - 1);
    }
    __syncthreads();

    // last block: final deterministic reduction over all partials
    if (slast) {
        __threadfence();
        float ps = 0.f, ns = 0.f, pc = 0.f, nc = 0.f;
        for (int b = t; b < NBLK; b += 128) {
            ps += g_part[b * 4 + 0];
            ns += g_part[b * 4 + 1];
            pc += g_part[b * 4 + 2];
            nc += g_part[b * 4 + 3];
        }
        #pragma unroll
        for (int o = 16; o; o >>= 1) {
            ps += __shfl_xor_sync(0xffffffffu, ps, o);
            ns += __shfl_xor_sync(0xffffffffu, ns, o);
            pc += __shfl_xor_sync(0xffffffffu, pc, o);
            nc += __shfl_xor_sync(0xffffffffu, nc, o);
        }
        if ((t & 31) == 0) { rp[w] = ps; rn[w] = ns; cp[w] = (int)pc; cn[w] = (int)nc; }
        __syncthreads();
        if (t == 0) {
            float fps = (rp[0] + rp[1]) + (rp[2] + rp[3]);
            float fns = (rn[0] + rn[1]) + (rn[2] + rn[3]);
            float fpc = (float)((cp[0] + cp[1]) + (cp[2] + cp[3]));
            float fnc = (float)((cn[0] + cn[1]) + (cn[2] + cn[3]));
            out[0] = fps / fmaxf(fpc, 1.0f) + fns / fmaxf(fnc, 1.0f);
            g_ctr = 0;   // reset for next graph replay (deterministic)
        }
    }
}

// ---------------------------------------------------------------------------
extern "C" void kernel_launch(void* const* d_in, const int* in_sizes, int n_in,
                              void* d_out, int out_size) {
    const float* x = (const float*)d_in[0];
    const long long* pids = (const long long*)d_in[1];
    (void)in_sizes; (void)n_in; (void)out_size;

    k_stats<<<MCL, 256>>>(x);
    dim3 g2(GBI, GBJ);
    k_dist<<<g2, 128>>>(x, pids, (float*)d_out);
}

// round 3
// speedup vs baseline: 1.7665x; 1.0046x over previous
#include <cuda_runtime.h>

// Problem constants (fixed by setup_inputs: P=64, K=8, C=512, N=3*P*K=1536)
#define NROWS 1536
#define CDIM  512
#define MCL   192      // 3*P hard-cluster centers
#define GK    8        // instances per cluster
#define MARGIN_KL 6.0f
#define MID_N 1024     // NROWS//3*2
#define MID_M 128      // MCL//3*2
#define GBI   48       // gemm grid x (row tiles of 32)
#define GBJ   3        // gemm grid y (col tiles of 64)
#define NEPI  48       // epilogue blocks

// Static device scratch (no cudaMalloc allowed)
__device__ float g_xs[NROWS * CDIM];       // softmax(x)
__device__ float g_rowc[NROWS];            // ent_x[i] + lse[i]
__device__ float g_hcT[CDIM * MCL];        // hcen^T  (k-major: [k][j])
__device__ float g_lhT[CDIM * MCL];        // logh^T  (k-major: [k][j])
__device__ float g_enth[MCL];              // sum hcen*logh per cluster
__device__ float g_pd[2 * NROWS * MCL];    // GEMM partials: z=0 x.hcen, z=1 xs.logh
__device__ float g_part[NEPI * 4];         // epilogue per-block partials
__device__ unsigned int g_ctr = 0;         // completion counter (reset by last block)

// ---------------- packed f32x2 helpers (Blackwell) ----------------
__device__ __forceinline__ unsigned long long pk2(float lo, float hi) {
    unsigned long long r;
    asm("mov.b64 %0, {%1, %2};" : "=l"(r) : "f"(lo), "f"(hi));
    return r;
}
__device__ __forceinline__ void fma2(unsigned long long& d,
                                     unsigned long long a, unsigned long long b) {
    asm("fma.rn.f32x2 %0, %1, %2, %0;" : "+l"(d) : "l"(a), "l"(b));
}
__device__ __forceinline__ void upk2(unsigned long long v, float& lo, float& hi) {
    asm("mov.b64 {%0, %1}, %2;" : "=f"(lo), "=f"(hi) : "l"(v));
}

// ---------------------------------------------------------------------------
// Kernel 1: fused softmax stats + hard-cluster centers.
// 192 blocks (one per cluster) x 256 threads (warp w handles row 8*j + w).
// ---------------------------------------------------------------------------
__global__ void __launch_bounds__(256) k_stats(const float* __restrict__ x) {
    __shared__ float sxs[8][516];
    __shared__ float sred[8];
    const int j = blockIdx.x;
    const int t = threadIdx.x;
    const int w = t >> 5, lane = t & 31;
    const int row = j * GK + w;

    const float4* xr = reinterpret_cast<const float4*>(x + (size_t)row * CDIM);
    float4 v[4];
    #pragma unroll
    for (int q = 0; q < 4; q++) v[q] = xr[lane + 32 * q];

    float mx = -1e30f;
    #pragma unroll
    for (int q = 0; q < 4; q++)
        mx = fmaxf(mx, fmaxf(fmaxf(v[q].x, v[q].y), fmaxf(v[q].z, v[q].w)));
    #pragma unroll
    for (int o = 16; o; o >>= 1) mx = fmaxf(mx, __shfl_xor_sync(0xffffffffu, mx, o));

    float4 e[4];
    float s = 0.f;
    #pragma unroll
    for (int q = 0; q < 4; q++) {
        e[q].x = expf(v[q].x - mx); e[q].y = expf(v[q].y - mx);
        e[q].z = expf(v[q].z - mx); e[q].w = expf(v[q].w - mx);
        s += (e[q].x + e[q].y) + (e[q].z + e[q].w);
    }
    #pragma unroll
    for (int o = 16; o; o >>= 1) s += __shfl_xor_sync(0xffffffffu, s, o);

    const float lse = mx + logf(s);
    const float inv = 1.0f / s;

    float4* gx = reinterpret_cast<float4*>(g_xs + (size_t)row * CDIM);
    float4* sx = reinterpret_cast<float4*>(&sxs[w][0]);
    float ent = 0.f;
    #pragma unroll
    for (int q = 0; q < 4; q++) {
        float4 p = make_float4(e[q].x * inv, e[q].y * inv, e[q].z * inv, e[q].w * inv);
        gx[lane + 32 * q] = p;
        sx[lane + 32 * q] = p;
        ent += p.x * (v[q].x - lse) + p.y * (v[q].y - lse)
             + p.z * (v[q].z - lse) + p.w * (v[q].w - lse);
    }
    #pragma unroll
    for (int o = 16; o; o >>= 1) ent += __shfl_xor_sync(0xffffffffu, ent, o);
    if (lane == 0) g_rowc[row] = ent + lse;

    __syncthreads();

    float entp = 0.f;
    #pragma unroll
    for (int h = 0; h < 2; h++) {
        const int c = t + 256 * h;
        float hc = 0.f;
        #pragma unroll
        for (int r = 0; r < GK; r++) hc += sxs[r][c];
        hc *= (1.0f / (float)GK);
        const float l = logf(fmaxf(hc, 1e-9f));
        g_hcT[c * MCL + j] = hc;
        g_lhT[c * MCL + j] = l;
        entp += hc * l;
    }
    #pragma unroll
    for (int o = 16; o; o >>= 1) entp += __shfl_xor_sync(0xffffffffu, entp, o);
    if (lane == 0) sred[w] = entp;
    __syncthreads();
    if (t == 0) {
        float eh = 0.f;
        #pragma unroll
        for (int r = 0; r < 8; r++) eh += sred[r];
        g_enth[j] = eh;
    }
}

// ---------------------------------------------------------------------------
// Kernel 2: single-matrix GEMM tile -> partial products.
// z = blockIdx.z selects (x . hcen^T) or (xs . logh^T).
// Block tile 32x64, thread tile 4x4 (row-pair packed f32x2), 128 threads.
// Grid (48, 3, 2) = 288 blocks -> 2 CTAs/SM, 8 warps/SM.
// Per kk per thread: 1 LDS(a as ulonglong2) + 1 LDS(b) + 4 dup movs + 8 FFMA2.
// ---------------------------------------------------------------------------
__global__ void __launch_bounds__(128, 2) k_gemm(const float* __restrict__ x) {
    __shared__ float sa[32][36];   // [kk][row], pad 36 (16B-aligned rows)
    __shared__ float sb[32][64];   // [kk][j]

    const int bi = blockIdx.x;     // 0..47
    const int bj = blockIdx.y;     // 0..2
    const int z  = blockIdx.z;     // 0..1
    const int t  = threadIdx.x;
    const int ti = t >> 4;         // 0..7  rows ti*4..+3
    const int tj = t & 15;         // 0..15 cols tj*4..+3

    const float* __restrict__ A = z ? g_xs : x;
    const float* __restrict__ B = z ? g_lhT : g_hcT;
    float* __restrict__ outp = g_pd + (size_t)z * (NROWS * MCL);

    // loader mappings
    const int arow = t >> 2;        // 0..31
    const int acol = (t & 3) * 4;   // 0,4,8,12  (+16 for second half)

    unsigned long long acc[2][4];   // [rowpair][col]
    #pragma unroll
    for (int c = 0; c < 4; c++) { acc[0][c] = 0ull; acc[1][c] = 0ull; }

    float4 a0, a1, bst[4];

    // prefetch chunk 0
    {
        const size_t ga = (size_t)(bi * 32 + arow) * CDIM + acol;
        a0 = *reinterpret_cast<const float4*>(A + ga);
        a1 = *reinterpret_cast<const float4*>(A + ga + 16);
        #pragma unroll
        for (int sbk = 0; sbk < 4; sbk++) {
            const int idx = t + 128 * sbk;
            const int kk = idx >> 4, jf = (idx & 15) * 4;
            bst[sbk] = *reinterpret_cast<const float4*>(B + (size_t)kk * MCL + bj * 64 + jf);
        }
    }

    for (int ch = 0; ch < CDIM / 32; ch++) {
        sa[acol + 0][arow] = a0.x; sa[acol + 1][arow] = a0.y;
        sa[acol + 2][arow] = a0.z; sa[acol + 3][arow] = a0.w;
        sa[acol + 16][arow] = a1.x; sa[acol + 17][arow] = a1.y;
        sa[acol + 18][arow] = a1.z; sa[acol + 19][arow] = a1.w;
        #pragma unroll
        for (int sbk = 0; sbk < 4; sbk++) {
            const int idx = t + 128 * sbk;
            const int kk = idx >> 4, jf = (idx & 15) * 4;
            *reinterpret_cast<float4*>(&sb[kk][jf]) = bst[sbk];
        }
        __syncthreads();

        if (ch < CDIM / 32 - 1) {
            const int k0 = (ch + 1) * 32;
            const size_t ga = (size_t)(bi * 32 + arow) * CDIM + k0 + acol;
            a0 = *reinterpret_cast<const float4*>(A + ga);
            a1 = *reinterpret_cast<const float4*>(A + ga + 16);
            #pragma unroll
            for (int sbk = 0; sbk < 4; sbk++) {
                const int idx = t + 128 * sbk;
                const int kk = idx >> 4, jf = (idx & 15) * 4;
                bst[sbk] = *reinterpret_cast<const float4*>(B + (size_t)(k0 + kk) * MCL + bj * 64 + jf);
            }
        }

        #pragma unroll
        for (int kk = 0; kk < 32; kk++) {
            const ulonglong2 aa = *reinterpret_cast<const ulonglong2*>(&sa[kk][ti * 4]);
            const float4 bv = *reinterpret_cast<const float4*>(&sb[kk][tj * 4]);
            const unsigned long long b0 = pk2(bv.x, bv.x);
            const unsigned long long b1 = pk2(bv.y, bv.y);
            const unsigned long long b2 = pk2(bv.z, bv.z);
            const unsigned long long b3 = pk2(bv.w, bv.w);
            fma2(acc[0][0], aa.x, b0);
            fma2(acc[0][1], aa.x, b1);
            fma2(acc[0][2], aa.x, b2);
            fma2(acc[0][3], aa.x, b3);
            fma2(acc[1][0], aa.y, b0);
            fma2(acc[1][1], aa.y, b1);
            fma2(acc[1][2], aa.y, b2);
            fma2(acc[1][3], aa.y, b3);
        }
        __syncthreads();
    }

    // write 4x4 partial tile (row-major [i][j], coalesced 128B per half-warp)
    const int ibase = bi * 32 + ti * 4;
    const int jbase = bj * 64 + tj * 4;
    float4 r0, r1, r2, r3;
    upk2(acc[0][0], r0.x, r1.x); upk2(acc[0][1], r0.y, r1.y);
    upk2(acc[0][2], r0.z, r1.z); upk2(acc[0][3], r0.w, r1.w);
    upk2(acc[1][0], r2.x, r3.x); upk2(acc[1][1], r2.y, r3.y);
    upk2(acc[1][2], r2.z, r3.z); upk2(acc[1][3], r2.w, r3.w);
    *reinterpret_cast<float4*>(outp + (size_t)(ibase + 0) * MCL + jbase) = r0;
    *reinterpret_cast<float4*>(outp + (size_t)(ibase + 1) * MCL + jbase) = r1;
    *reinterpret_cast<float4*>(outp + (size_t)(ibase + 2) * MCL + jbase) = r2;
    *reinterpret_cast<float4*>(outp + (size_t)(ibase + 3) * MCL + jbase) = r3;
}

// ---------------------------------------------------------------------------
// Kernel 3: epilogue. dist = rowc[i] + enth[j] - pd0 - pd1; classify + reduce.
// 48 blocks x 256 threads; block b handles rows b*32..+31, all 192 cols.
// Last block performs the final deterministic reduction.
// ---------------------------------------------------------------------------
__global__ void __launch_bounds__(256) k_epi(const long long* __restrict__ pids,
                                             float* __restrict__ out) {
    __shared__ float senth[MCL];
    __shared__ long long sph[MCL];
    __shared__ float srowc[32];
    __shared__ long long spid[32];
    __shared__ float rp[8], rn[8];
    __shared__ int cp[8], cn[8];
    __shared__ bool slast;

    const int b = blockIdx.x;
    const int t = threadIdx.x;
    const int ibase = b * 32;

    if (t < MCL) {
        senth[t] = g_enth[t];
        sph[t] = pids[(size_t)t * GK];
    }
    if (t >= 192 && t < 224) {
        const int r = t - 192;
        srowc[r] = g_rowc[ibase + r];
        spid[r] = pids[ibase + r];
    }
    __syncthreads();

    float psum = 0.f, nsum = 0.f;
    int pcnt = 0, ncnt = 0;
    #pragma unroll
    for (int q = 0; q < 6; q++) {
        const int idx = t + 256 * q;          // 0..1535 (float4 index)
        const int r = idx / 48;               // row in tile
        const int j = (idx % 48) * 4;         // col
        const int i = ibase + r;
        const float4 p0 = *reinterpret_cast<const float4*>(g_pd + (size_t)i * MCL + j);
        const float4 p1 = *reinterpret_cast<const float4*>(g_pd + (size_t)(NROWS * MCL) + (size_t)i * MCL + j);
        const float rc = srowc[r];
        const long long pi = spid[r];
        const bool itop = i < MID_N;
        const float d0 = rc + senth[j + 0] - p0.x - p1.x;
        const float d1 = rc + senth[j + 1] - p0.y - p1.y;
        const float d2 = rc + senth[j + 2] - p0.z - p1.z;
        const float d3 = rc + senth[j + 3] - p0.w - p1.w;
        const float dv[4] = { d0, d1, d2, d3 };
        #pragma unroll
        for (int c = 0; c < 4; c++) {
            const bool mask = (pi == sph[j + c]);
            const bool region = itop != ((j + c) < MID_M);
            if (mask) {
                if (region) { psum += dv[c]; pcnt++; }
            } else {
                nsum += fmaxf(MARGIN_KL - dv[c], 0.f);
                ncnt++;
            }
        }
    }

    // deterministic block reduction
    #pragma unroll
    for (int o = 16; o; o >>= 1) {
        psum += __shfl_xor_sync(0xffffffffu, psum, o);
        nsum += __shfl_xor_sync(0xffffffffu, nsum, o);
        pcnt += __shfl_xor_sync(0xffffffffu, pcnt, o);
        ncnt += __shfl_xor_sync(0xffffffffu, ncnt, o);
    }
    const int w = t >> 5;
    if ((t & 31) == 0) { rp[w] = psum; rn[w] = nsum; cp[w] = pcnt; cn[w] = ncnt; }
    __syncthreads();
    if (t == 0) {
        float fp = 0.f, fn = 0.f; int ip = 0, in_ = 0;
        #pragma unroll
        for (int q = 0; q < 8; q++) { fp += rp[q]; fn += rn[q]; ip += cp[q]; in_ += cn[q]; }
        g_part[b * 4 + 0] = fp;
        g_part[b * 4 + 1] = fn;
        g_part[b * 4 + 2] = (float)ip;
        g_part[b * 4 + 3] = (float)in_;
        __threadfence();
        slast = (atomicAdd(&g_ctr, 1u) == NEPI - 1);
    }
    __syncthreads();

    if (slast) {
        __threadfence();
        float ps = 0.f, ns = 0.f, pc = 0.f, nc = 0.f;
        if (t < NEPI) {
            ps = g_part[t * 4 + 0];
            ns = g_part[t * 4 + 1];
            pc = g_part[t * 4 + 2];
            nc = g_part[t * 4 + 3];
        }
        #pragma unroll
        for (int o = 16; o; o >>= 1) {
            ps += __shfl_xor_sync(0xffffffffu, ps, o);
            ns += __shfl_xor_sync(0xffffffffu, ns, o);
            pc += __shfl_xor_sync(0xffffffffu, pc, o);
            nc += __shfl_xor_sync(0xffffffffu, nc, o);
        }
        if ((t & 31) == 0) { rp[w] = ps; rn[w] = ns; cp[w] = (int)pc; cn[w] = (int)nc; }
        __syncthreads();
        if (t == 0) {
            float fps = 0.f, fns = 0.f, fpc = 0.f, fnc = 0.f;
            #pragma unroll
            for (int q = 0; q < 8; q++) {
                fps += rp[q]; fns += rn[q];
                fpc += (float)cp[q]; fnc += (float)cn[q];
            }
            out[0] = fps / fmaxf(fpc, 1.0f) + fns / fmaxf(fnc, 1.0f);
            g_ctr = 0;   // reset for next graph replay
        }
    }
}

// ---------------------------------------------------------------------------
extern "C" void kernel_launch(void* const* d_in, const int* in_sizes, int n_in,
                              void* d_out, int out_size) {
    const float* x = (const float*)d_in[0];
    const long long* pids = (const long long*)d_in[1];
    (void)in_sizes; (void)n_in; (void)out_size;

    k_stats<<<MCL, 256>>>(x);
    dim3 gg(GBI, GBJ, 2);
    k_gemm<<<gg, 128>>>(x);
    k_epi<<<NEPI, 256>>>(pids, (float*)d_out);
}